// round 4
// baseline (speedup 1.0000x reference)
#include <cuda_runtime.h>
#include <math.h>

#define NMAX 100000
#define EMAX 1600000

// ---------------- scratch (allocation-free: __device__ globals) ----------------
__device__ float g_bufA[(size_t)NMAX * 128];
__device__ float g_bufB[(size_t)NMAX * 128];
__device__ float g_deg[NMAX];
__device__ float g_dinv[NMAX];
__device__ int   g_cnt[NMAX];
__device__ int   g_fill[NMAX];
__device__ int   g_rowptr[NMAX + 1];
__device__ int   g_col[EMAX];
__device__ float g_coef[EMAX];
__device__ int   g_csum[128];
__device__ float g_sum[128];
__device__ float g_sumsq[128];
__device__ float g_scale[128];
__device__ float g_shift[128];

__device__ __forceinline__ const float* sel_src(int s, const float* ext) {
    return (s == 0) ? ext : ((s == 1) ? g_bufA : g_bufB);
}
__device__ __forceinline__ float* sel_dst(int s, float* ext) {
    return (s == 0) ? ext : ((s == 1) ? g_bufA : g_bufB);
}

// ---------------- graph preprocessing ----------------
__global__ void k_init(int n) {
    int v = blockIdx.x * blockDim.x + threadIdx.x;
    if (v < n) { g_deg[v] = 1.0f; g_cnt[v] = 0; g_fill[v] = 0; }
}

// edge_index arrives as int32 [2, E]: row 0 = src, row 1 = dst
__global__ void k_hist(const int* __restrict__ ei, const float* __restrict__ w, int E, int n) {
    int e = blockIdx.x * blockDim.x + threadIdx.x;
    if (e < E) {
        int dst = ei[E + e];
        if ((unsigned)dst < (unsigned)n) {
            atomicAdd(&g_deg[dst], w[e]);
            atomicAdd(&g_cnt[dst], 1);
        }
    }
}

__global__ void k_dinv(int n) {
    int v = blockIdx.x * blockDim.x + threadIdx.x;
    if (v < n) g_dinv[v] = rsqrtf(g_deg[v]);   // deg >= 1 always (self loop weight 1)
}

// per-chunk sums (chunk = 1024 nodes)
__global__ void k_scanA(int n) {
    __shared__ int sh[1024];
    int t = threadIdx.x;
    int idx = blockIdx.x * 1024 + t;
    sh[t] = (idx < n) ? g_cnt[idx] : 0;
    __syncthreads();
    for (int off = 512; off > 0; off >>= 1) {
        if (t < off) sh[t] += sh[t + off];
        __syncthreads();
    }
    if (t == 0) g_csum[blockIdx.x] = sh[0];
}

// exclusive scan of chunk sums (nc <= 128)
__global__ void k_scanB(int nc, int n) {
    __shared__ int sh[128];
    int t = threadIdx.x;
    int v = (t < nc) ? g_csum[t] : 0;
    sh[t] = v; __syncthreads();
    for (int off = 1; off < 128; off <<= 1) {
        int x = (t >= off) ? sh[t - off] : 0;
        __syncthreads();
        sh[t] += x;
        __syncthreads();
    }
    if (t < nc) g_csum[t] = sh[t] - v;       // exclusive
    if (t == nc - 1) g_rowptr[n] = sh[t];    // total
}

__global__ void k_scanC(int n) {
    __shared__ int sh[1024];
    int t = threadIdx.x;
    int idx = blockIdx.x * 1024 + t;
    int val = (idx < n) ? g_cnt[idx] : 0;
    sh[t] = val; __syncthreads();
    for (int off = 1; off < 1024; off <<= 1) {
        int x = (t >= off) ? sh[t - off] : 0;
        __syncthreads();
        sh[t] += x;
        __syncthreads();
    }
    if (idx < n) g_rowptr[idx] = g_csum[blockIdx.x] + sh[t] - val; // exclusive
}

__global__ void k_fill(const int* __restrict__ ei, const float* __restrict__ w, int E, int n) {
    int e = blockIdx.x * blockDim.x + threadIdx.x;
    if (e < E) {
        int s = ei[e];
        int d = ei[E + e];
        if ((unsigned)s < (unsigned)n && (unsigned)d < (unsigned)n) {
            int pos = g_rowptr[d] + atomicAdd(&g_fill[d], 1);
            g_col[pos]  = s;
            g_coef[pos] = g_dinv[s] * w[e] * g_dinv[d];
        }
    }
}

// ---------------- GEMM: [n,128] @ [128,NC], fused BN(scale,shift)+ReLU on input ----------------
// 256 threads (tx=t&15, ty=t>>4); tile 128 rows x NC cols; K chunked by 32.
// Static smem: xs 18432B + ws (32*NC*4)B  ->  <= 34816B (NC=128), no attribute needed.
template<int NC>
__global__ void k_gemm(const float* __restrict__ Xext, int xsel,
                       const float* __restrict__ W, int osel, int n, int useBN) {
    __shared__ float xs[128][36];
    __shared__ float ws[32][NC];

    const float* X = sel_src(xsel, Xext);
    float*       O = sel_dst(osel, nullptr);

    const int t  = threadIdx.x;
    const int tx = t & 15;
    const int ty = t >> 4;
    const int rowBase = blockIdx.x * 128;
    const int RN = NC / 16;

    float acc[8][RN];
    #pragma unroll
    for (int i = 0; i < 8; i++)
        #pragma unroll
        for (int j = 0; j < RN; j++) acc[i][j] = 0.f;

    const float4* X4 = (const float4*)X;
    const float4* W4 = (const float4*)W;

    for (int kc = 0; kc < 4; kc++) {
        // X tile: 128 rows x 32 cols of this K-chunk (8 float4 per row)
        #pragma unroll
        for (int i4 = t; i4 < 128 * 8; i4 += 256) {
            int r  = i4 >> 3;
            int c4 = i4 & 7;
            int grow = rowBase + r;
            float4 v = make_float4(0.f, 0.f, 0.f, 0.f);
            if (grow < n) v = X4[(size_t)grow * 32 + kc * 8 + c4];
            if (useBN) {
                int k = kc * 32 + c4 * 4;
                v.x = fmaxf(fmaf(v.x, g_scale[k],     g_shift[k]),     0.f);
                v.y = fmaxf(fmaf(v.y, g_scale[k + 1], g_shift[k + 1]), 0.f);
                v.z = fmaxf(fmaf(v.z, g_scale[k + 2], g_shift[k + 2]), 0.f);
                v.w = fmaxf(fmaf(v.w, g_scale[k + 3], g_shift[k + 3]), 0.f);
            }
            *(float4*)&xs[r][c4 * 4] = v;   // row stride 144B -> 16B aligned
        }
        // W chunk: rows [kc*32, kc*32+32)
        #pragma unroll
        for (int i4 = t; i4 < 32 * NC / 4; i4 += 256) {
            int r  = i4 / (NC / 4);
            int c4 = i4 % (NC / 4);
            *(float4*)&ws[r][c4 * 4] = W4[(size_t)(kc * 32 + r) * (NC / 4) + c4];
        }
        __syncthreads();

        #pragma unroll 8
        for (int k2 = 0; k2 < 32; k2++) {
            float a[8];
            #pragma unroll
            for (int i = 0; i < 8; i++) a[i] = xs[ty + 16 * i][k2];
            float b[RN];
            #pragma unroll
            for (int j = 0; j < RN; j++) b[j] = ws[k2][tx + 16 * j];
            #pragma unroll
            for (int i = 0; i < 8; i++)
                #pragma unroll
                for (int j = 0; j < RN; j++)
                    acc[i][j] = fmaf(a[i], b[j], acc[i][j]);
        }
        __syncthreads();
    }

    #pragma unroll
    for (int i = 0; i < 8; i++) {
        int r = rowBase + ty + 16 * i;
        if (r < n) {
            #pragma unroll
            for (int j = 0; j < RN; j++)
                O[(size_t)r * NC + tx + 16 * j] = acc[i][j];
        }
    }
}

// ---------------- aggregation: out[v] = sum_in coef*h[src] + dinv[v]^2*h[v] + bias ----------------
template<int D>
__global__ void k_agg(int hsel, const float* __restrict__ bias,
                      float* __restrict__ Oext, int osel, int n) {
    const int TPN = D / 4;
    int gid  = blockIdx.x * blockDim.x + threadIdx.x;
    int v    = gid / TPN;
    int lane = gid % TPN;
    if (v >= n) return;

    const float4* H4 = (const float4*)sel_src(hsel, nullptr);
    float4*       O4 = (float4*)sel_dst(osel, Oext);

    float dv = g_dinv[v];
    float sc = dv * dv;
    float4 h = H4[(size_t)v * TPN + lane];
    float4 acc = make_float4(h.x * sc, h.y * sc, h.z * sc, h.w * sc);

    int p   = g_rowptr[v];
    int end = g_rowptr[v + 1];
    for (; p + 2 <= end; p += 2) {
        int c0 = g_col[p];     float w0 = g_coef[p];
        int c1 = g_col[p + 1]; float w1 = g_coef[p + 1];
        float4 m0 = H4[(size_t)c0 * TPN + lane];
        float4 m1 = H4[(size_t)c1 * TPN + lane];
        acc.x = fmaf(w0, m0.x, acc.x); acc.y = fmaf(w0, m0.y, acc.y);
        acc.z = fmaf(w0, m0.z, acc.z); acc.w = fmaf(w0, m0.w, acc.w);
        acc.x = fmaf(w1, m1.x, acc.x); acc.y = fmaf(w1, m1.y, acc.y);
        acc.z = fmaf(w1, m1.z, acc.z); acc.w = fmaf(w1, m1.w, acc.w);
    }
    if (p < end) {
        int c = g_col[p]; float w = g_coef[p];
        float4 m = H4[(size_t)c * TPN + lane];
        acc.x = fmaf(w, m.x, acc.x); acc.y = fmaf(w, m.y, acc.y);
        acc.z = fmaf(w, m.z, acc.z); acc.w = fmaf(w, m.w, acc.w);
    }

    float4 b4 = ((const float4*)bias)[lane];
    acc.x += b4.x; acc.y += b4.y; acc.z += b4.z; acc.w += b4.w;
    O4[(size_t)v * TPN + lane] = acc;
}

// ---------------- BatchNorm stats / finalize (stats always on g_bufB) ----------------
__global__ void k_zstats() {
    int c = threadIdx.x;
    g_sum[c] = 0.f; g_sumsq[c] = 0.f;
}

__global__ void k_stats(int n) {
    int t = threadIdx.x;
    int col = t & 127;
    int phase = t >> 7;  // 0/1
    float s = 0.f, sq = 0.f;
    for (int r = blockIdx.x * 2 + phase; r < n; r += gridDim.x * 2) {
        float v = g_bufB[(size_t)r * 128 + col];
        s += v; sq += v * v;
    }
    __shared__ float ssum[256], ssq[256];
    ssum[t] = s; ssq[t] = sq;
    __syncthreads();
    if (t < 128) {
        atomicAdd(&g_sum[t],   ssum[t] + ssum[t + 128]);
        atomicAdd(&g_sumsq[t], ssq[t]  + ssq[t + 128]);
    }
}

__global__ void k_bnfin(const float* __restrict__ gamma, const float* __restrict__ beta, int n) {
    int c = threadIdx.x;
    double mean = (double)g_sum[c] / (double)n;
    double var  = (double)g_sumsq[c] / (double)n - mean * mean;
    float s = (float)((double)gamma[c] / sqrt(var + 1e-5));
    g_scale[c] = s;
    g_shift[c] = (float)((double)beta[c] - mean * (double)s);
}

// ---------------- launcher ----------------
extern "C" void kernel_launch(void* const* d_in, const int* in_sizes, int n_in,
                              void* d_out, int out_size) {
    const float* x  = (const float*)d_in[0];
    const int*   ei = (const int*)d_in[1];     // int32 [2, E]
    const float* w  = (const float*)d_in[2];
    const float* W1 = (const float*)d_in[3];
    const float* b1 = (const float*)d_in[4];
    const float* W2 = (const float*)d_in[5];
    const float* b2 = (const float*)d_in[6];
    const float* W3 = (const float*)d_in[7];
    const float* b3 = (const float*)d_in[8];
    const float* gamma1 = (const float*)d_in[9];
    const float* beta1  = (const float*)d_in[10];
    const float* gamma2 = (const float*)d_in[11];
    const float* beta2  = (const float*)d_in[12];

    int n = in_sizes[0] / 128;
    int E = in_sizes[1] / 2;    // edge_index has 2*E elements
    float* out = (float*)d_out;

    int nb_n = (n + 255) / 256;
    int nb_e = (E + 255) / 256;
    int nc   = (n + 1023) / 1024;
    int gemm_grid = (n + 127) / 128;

    // graph preprocessing (CSR by dst + normalization coefs)
    k_init<<<nb_n, 256>>>(n);
    k_hist<<<nb_e, 256>>>(ei, w, E, n);
    k_dinv<<<nb_n, 256>>>(n);
    k_scanA<<<nc, 1024>>>(n);
    k_scanB<<<1, 128>>>(nc, n);
    k_scanC<<<nc, 1024>>>(n);
    k_fill<<<nb_e, 256>>>(ei, w, E, n);

    // layer 1: gemm(x) -> bufA, agg -> bufB, BN stats
    k_gemm<128><<<gemm_grid, 256>>>(x, 0, W1, 1, n, 0);
    k_agg<128><<<(n * 32 + 255) / 256, 256>>>(1, b1, nullptr, 2, n);
    k_zstats<<<1, 128>>>();
    k_stats<<<400, 256>>>(n);
    k_bnfin<<<1, 128>>>(gamma1, beta1, n);

    // layer 2: gemm(BN+ReLU(bufB)) -> bufA, agg -> bufB, BN stats
    k_gemm<128><<<gemm_grid, 256>>>(nullptr, 2, W2, 1, n, 1);
    k_agg<128><<<(n * 32 + 255) / 256, 256>>>(1, b2, nullptr, 2, n);
    k_zstats<<<1, 128>>>();
    k_stats<<<400, 256>>>(n);
    k_bnfin<<<1, 128>>>(gamma2, beta2, n);

    // layer 3: gemm(BN+ReLU(bufB)) -> bufA (64 cols), agg -> out
    k_gemm<64><<<gemm_grid, 256>>>(nullptr, 2, W3, 1, n, 1);
    k_agg<64><<<(n * 16 + 255) / 256, 256>>>(1, b3, out, 0, n);
}

// round 9
// speedup vs baseline: 1.1976x; 1.1976x over previous
#include <cuda_runtime.h>
#include <cuda_bf16.h>
#include <stdint.h>
#include <math.h>

#define NMAX 100000
#define EMAX 1600000

// ---------------- scratch (allocation-free: __device__ globals) ----------------
__device__ float g_bufA[(size_t)NMAX * 128];
__device__ float g_bufB[(size_t)NMAX * 128];
__device__ float g_deg[NMAX];
__device__ float g_dinv[NMAX];
__device__ int   g_cnt[NMAX];
__device__ int   g_fill[NMAX];
__device__ int   g_rowptr[NMAX + 1];
__device__ int   g_col[EMAX];
__device__ float g_coef[EMAX];
__device__ int   g_csum[128];
__device__ float g_sum[128];
__device__ float g_sumsq[128];
__device__ float g_scale[128];
__device__ float g_shift[128];

__device__ __forceinline__ const float* sel_src(int s, const float* ext) {
    return (s == 0) ? ext : ((s == 1) ? g_bufA : g_bufB);
}
__device__ __forceinline__ float* sel_dst(int s, float* ext) {
    return (s == 0) ? ext : ((s == 1) ? g_bufA : g_bufB);
}

// ---------------- graph preprocessing ----------------
__global__ void k_init(int n) {
    int v = blockIdx.x * blockDim.x + threadIdx.x;
    if (v < n) { g_deg[v] = 1.0f; g_cnt[v] = 0; g_fill[v] = 0; }
}

// edge_index arrives as int32 [2, E]: row 0 = src, row 1 = dst
__global__ void k_hist(const int* __restrict__ ei, const float* __restrict__ w, int E, int n) {
    int e = blockIdx.x * blockDim.x + threadIdx.x;
    if (e < E) {
        int dst = ei[E + e];
        if ((unsigned)dst < (unsigned)n) {
            atomicAdd(&g_deg[dst], w[e]);
            atomicAdd(&g_cnt[dst], 1);
        }
    }
}

__global__ void k_dinv(int n) {
    int v = blockIdx.x * blockDim.x + threadIdx.x;
    if (v < n) g_dinv[v] = rsqrtf(g_deg[v]);
}

__global__ void k_scanA(int n) {
    __shared__ int sh[1024];
    int t = threadIdx.x;
    int idx = blockIdx.x * 1024 + t;
    sh[t] = (idx < n) ? g_cnt[idx] : 0;
    __syncthreads();
    for (int off = 512; off > 0; off >>= 1) {
        if (t < off) sh[t] += sh[t + off];
        __syncthreads();
    }
    if (t == 0) g_csum[blockIdx.x] = sh[0];
}

__global__ void k_scanB(int nc, int n) {
    __shared__ int sh[128];
    int t = threadIdx.x;
    int v = (t < nc) ? g_csum[t] : 0;
    sh[t] = v; __syncthreads();
    for (int off = 1; off < 128; off <<= 1) {
        int x = (t >= off) ? sh[t - off] : 0;
        __syncthreads();
        sh[t] += x;
        __syncthreads();
    }
    if (t < nc) g_csum[t] = sh[t] - v;
    if (t == nc - 1) g_rowptr[n] = sh[t];
}

__global__ void k_scanC(int n) {
    __shared__ int sh[1024];
    int t = threadIdx.x;
    int idx = blockIdx.x * 1024 + t;
    int val = (idx < n) ? g_cnt[idx] : 0;
    sh[t] = val; __syncthreads();
    for (int off = 1; off < 1024; off <<= 1) {
        int x = (t >= off) ? sh[t - off] : 0;
        __syncthreads();
        sh[t] += x;
        __syncthreads();
    }
    if (idx < n) g_rowptr[idx] = g_csum[blockIdx.x] + sh[t] - val;
}

__global__ void k_fill(const int* __restrict__ ei, const float* __restrict__ w, int E, int n) {
    int e = blockIdx.x * blockDim.x + threadIdx.x;
    if (e < E) {
        int s = ei[e];
        int d = ei[E + e];
        if ((unsigned)s < (unsigned)n && (unsigned)d < (unsigned)n) {
            int pos = g_rowptr[d] + atomicAdd(&g_fill[d], 1);
            g_col[pos]  = s;
            g_coef[pos] = g_dinv[s] * w[e] * g_dinv[d];
        }
    }
}

// ---------------- tensor-core GEMM: [n,128] @ [128,NC] via bf16 split ----------------
// X = Xh + Xl, W = Wh + Wl (bf16).  O = Xh*Wh + Xh*Wl + Xl*Wh  (err ~2^-16).
// 256 threads / 8 warps; M tile 128, K chunked by 32; fused BN+ReLU on input.
// Smem 40KB static (NC=128). A stride 40 bf16 -> conflict-free frag loads.

__device__ __forceinline__ void mma16816(float* d, const uint32_t* a, const uint32_t* b) {
    asm volatile(
        "mma.sync.aligned.m16n8k16.row.col.f32.bf16.bf16.f32 "
        "{%0,%1,%2,%3}, {%4,%5,%6,%7}, {%8,%9}, {%0,%1,%2,%3};\n"
        : "+f"(d[0]), "+f"(d[1]), "+f"(d[2]), "+f"(d[3])
        : "r"(a[0]), "r"(a[1]), "r"(a[2]), "r"(a[3]), "r"(b[0]), "r"(b[1]));
}

__device__ __forceinline__ void split_bf16(float f, __nv_bfloat16& h, __nv_bfloat16& l) {
    h = __float2bfloat16(f);
    l = __float2bfloat16(f - __bfloat162float(h));
}

template<int NC>
__global__ void k_gemm(const float* __restrict__ Xext, int xsel,
                       const float* __restrict__ W, int osel, int n, int useBN) {
    __shared__ __nv_bfloat16 sAh[128][40];
    __shared__ __nv_bfloat16 sAl[128][40];
    __shared__ __nv_bfloat16 sBh[NC][40];   // transposed: [n][k]
    __shared__ __nv_bfloat16 sBl[NC][40];

    const float* X = sel_src(xsel, Xext);
    float*       O = sel_dst(osel, nullptr);

    const int t    = threadIdx.x;
    const int wid  = t >> 5;
    const int lane = t & 31;
    const int qr   = lane >> 2;        // 0..7
    const int qc   = (lane & 3) * 2;   // 0,2,4,6
    const int rowBase = blockIdx.x * 128;

    constexpr int M_TILES = (NC == 128) ? 2 : 1;     // warp tile rows / 16
    const int mrow0 = (NC == 128) ? ((wid & 3) * 32) : (wid * 16);
    const int ncol0 = (NC == 128) ? ((wid >> 2) * 64) : 0;

    float d[M_TILES][8][4];
    #pragma unroll
    for (int mt = 0; mt < M_TILES; mt++)
        #pragma unroll
        for (int nt = 0; nt < 8; nt++)
            #pragma unroll
            for (int j = 0; j < 4; j++) d[mt][nt][j] = 0.f;

    const float4* X4 = (const float4*)X;

    for (int kc = 0; kc < 4; kc++) {
        // ---- fill A chunk: rows 0..127, k kc*32..+31 ----
        #pragma unroll
        for (int it = 0; it < 4; it++) {
            int r  = (t >> 3) + it * 32;
            int c4 = t & 7;                 // float4 within chunk
            int grow = rowBase + r;
            float4 v = make_float4(0.f, 0.f, 0.f, 0.f);
            if (grow < n) v = X4[(size_t)grow * 32 + kc * 8 + c4];
            if (useBN) {
                int k = kc * 32 + c4 * 4;
                v.x = fmaxf(fmaf(v.x, g_scale[k],     g_shift[k]),     0.f);
                v.y = fmaxf(fmaf(v.y, g_scale[k + 1], g_shift[k + 1]), 0.f);
                v.z = fmaxf(fmaf(v.z, g_scale[k + 2], g_shift[k + 2]), 0.f);
                v.w = fmaxf(fmaf(v.w, g_scale[k + 3], g_shift[k + 3]), 0.f);
            }
            __nv_bfloat16 h0,l0,h1,l1,h2,l2,h3,l3;
            split_bf16(v.x, h0, l0); split_bf16(v.y, h1, l1);
            split_bf16(v.z, h2, l2); split_bf16(v.w, h3, l3);
            int kk = c4 * 4;
            sAh[r][kk]   = h0; sAh[r][kk+1] = h1; sAh[r][kk+2] = h2; sAh[r][kk+3] = h3;
            sAl[r][kk]   = l0; sAl[r][kk+1] = l1; sAl[r][kk+2] = l2; sAl[r][kk+3] = l3;
        }
        // ---- fill B chunk (transpose): W[kc*32+k][nn] -> sB[nn][k] ----
        #pragma unroll
        for (int it = 0; it < 32 * NC / 256; it++) {
            int idx = t + it * 256;
            int k  = idx / NC;
            int nn = idx % NC;
            float wv = W[(size_t)(kc * 32 + k) * NC + nn];
            __nv_bfloat16 h, l;
            split_bf16(wv, h, l);
            sBh[nn][k] = h;
            sBl[nn][k] = l;
        }
        __syncthreads();

        // ---- 2 k-steps of 16 ----
        #pragma unroll
        for (int ks = 0; ks < 2; ks++) {
            int kb = ks * 16;
            uint32_t ah[M_TILES][4], al[M_TILES][4];
            #pragma unroll
            for (int mt = 0; mt < M_TILES; mt++) {
                int r0 = mrow0 + mt * 16 + qr;
                ah[mt][0] = *(const uint32_t*)&sAh[r0    ][kb + qc];
                ah[mt][1] = *(const uint32_t*)&sAh[r0 + 8][kb + qc];
                ah[mt][2] = *(const uint32_t*)&sAh[r0    ][kb + qc + 8];
                ah[mt][3] = *(const uint32_t*)&sAh[r0 + 8][kb + qc + 8];
                al[mt][0] = *(const uint32_t*)&sAl[r0    ][kb + qc];
                al[mt][1] = *(const uint32_t*)&sAl[r0 + 8][kb + qc];
                al[mt][2] = *(const uint32_t*)&sAl[r0    ][kb + qc + 8];
                al[mt][3] = *(const uint32_t*)&sAl[r0 + 8][kb + qc + 8];
            }
            uint32_t bh[8][2], bl[8][2];
            #pragma unroll
            for (int nt = 0; nt < 8; nt++) {
                int n0 = ncol0 + nt * 8 + qr;
                bh[nt][0] = *(const uint32_t*)&sBh[n0][kb + qc];
                bh[nt][1] = *(const uint32_t*)&sBh[n0][kb + qc + 8];
                bl[nt][0] = *(const uint32_t*)&sBl[n0][kb + qc];
                bl[nt][1] = *(const uint32_t*)&sBl[n0][kb + qc + 8];
            }
            #pragma unroll
            for (int mt = 0; mt < M_TILES; mt++)
                #pragma unroll
                for (int nt = 0; nt < 8; nt++) {
                    mma16816(d[mt][nt], ah[mt], bh[nt]);
                    mma16816(d[mt][nt], ah[mt], bl[nt]);
                    mma16816(d[mt][nt], al[mt], bh[nt]);
                }
        }
        __syncthreads();
    }

    // ---- epilogue ----
    #pragma unroll
    for (int mt = 0; mt < M_TILES; mt++) {
        #pragma unroll
        for (int nt = 0; nt < 8; nt++) {
            int r = rowBase + mrow0 + mt * 16 + qr;
            int c = ncol0 + nt * 8 + qc;
            if (r < n)
                *(float2*)&O[(size_t)r * NC + c] = make_float2(d[mt][nt][0], d[mt][nt][1]);
            if (r + 8 < n)
                *(float2*)&O[(size_t)(r + 8) * NC + c] = make_float2(d[mt][nt][2], d[mt][nt][3]);
        }
    }
}

// ---------------- aggregation: out[v] = sum_in coef*h[src] + dinv[v]^2*h[v] + bias ----------------
template<int D>
__global__ void k_agg(int hsel, const float* __restrict__ bias,
                      float* __restrict__ Oext, int osel, int n) {
    const int TPN = D / 4;
    int gid  = blockIdx.x * blockDim.x + threadIdx.x;
    int v    = gid / TPN;
    int lane = gid % TPN;
    if (v >= n) return;

    const float4* H4 = (const float4*)sel_src(hsel, nullptr);
    float4*       O4 = (float4*)sel_dst(osel, Oext);

    float dv = g_dinv[v];
    float sc = dv * dv;
    float4 h = H4[(size_t)v * TPN + lane];
    float4 acc = make_float4(h.x * sc, h.y * sc, h.z * sc, h.w * sc);

    int p   = g_rowptr[v];
    int end = g_rowptr[v + 1];
    for (; p + 2 <= end; p += 2) {
        int c0 = g_col[p];     float w0 = g_coef[p];
        int c1 = g_col[p + 1]; float w1 = g_coef[p + 1];
        float4 m0 = H4[(size_t)c0 * TPN + lane];
        float4 m1 = H4[(size_t)c1 * TPN + lane];
        acc.x = fmaf(w0, m0.x, acc.x); acc.y = fmaf(w0, m0.y, acc.y);
        acc.z = fmaf(w0, m0.z, acc.z); acc.w = fmaf(w0, m0.w, acc.w);
        acc.x = fmaf(w1, m1.x, acc.x); acc.y = fmaf(w1, m1.y, acc.y);
        acc.z = fmaf(w1, m1.z, acc.z); acc.w = fmaf(w1, m1.w, acc.w);
    }
    if (p < end) {
        int c = g_col[p]; float w = g_coef[p];
        float4 m = H4[(size_t)c * TPN + lane];
        acc.x = fmaf(w, m.x, acc.x); acc.y = fmaf(w, m.y, acc.y);
        acc.z = fmaf(w, m.z, acc.z); acc.w = fmaf(w, m.w, acc.w);
    }

    float4 b4 = ((const float4*)bias)[lane];
    acc.x += b4.x; acc.y += b4.y; acc.z += b4.z; acc.w += b4.w;
    O4[(size_t)v * TPN + lane] = acc;
}

// ---------------- BatchNorm stats / finalize (stats always on g_bufB) ----------------
__global__ void k_zstats() {
    int c = threadIdx.x;
    g_sum[c] = 0.f; g_sumsq[c] = 0.f;
}

__global__ void k_stats(int n) {
    int t = threadIdx.x;
    int col = t & 127;
    int phase = t >> 7;
    float s = 0.f, sq = 0.f;
    for (int r = blockIdx.x * 2 + phase; r < n; r += gridDim.x * 2) {
        float v = g_bufB[(size_t)r * 128 + col];
        s += v; sq += v * v;
    }
    __shared__ float ssum[256], ssq[256];
    ssum[t] = s; ssq[t] = sq;
    __syncthreads();
    if (t < 128) {
        atomicAdd(&g_sum[t],   ssum[t] + ssum[t + 128]);
        atomicAdd(&g_sumsq[t], ssq[t]  + ssq[t + 128]);
    }
}

__global__ void k_bnfin(const float* __restrict__ gamma, const float* __restrict__ beta, int n) {
    int c = threadIdx.x;
    double mean = (double)g_sum[c] / (double)n;
    double var  = (double)g_sumsq[c] / (double)n - mean * mean;
    float s = (float)((double)gamma[c] / sqrt(var + 1e-5));
    g_scale[c] = s;
    g_shift[c] = (float)((double)beta[c] - mean * (double)s);
}

// ---------------- launcher ----------------
extern "C" void kernel_launch(void* const* d_in, const int* in_sizes, int n_in,
                              void* d_out, int out_size) {
    const float* x  = (const float*)d_in[0];
    const int*   ei = (const int*)d_in[1];     // int32 [2, E]
    const float* w  = (const float*)d_in[2];
    const float* W1 = (const float*)d_in[3];
    const float* b1 = (const float*)d_in[4];
    const float* W2 = (const float*)d_in[5];
    const float* b2 = (const float*)d_in[6];
    const float* W3 = (const float*)d_in[7];
    const float* b3 = (const float*)d_in[8];
    const float* gamma1 = (const float*)d_in[9];
    const float* beta1  = (const float*)d_in[10];
    const float* gamma2 = (const float*)d_in[11];
    const float* beta2  = (const float*)d_in[12];

    int n = in_sizes[0] / 128;
    int E = in_sizes[1] / 2;
    float* out = (float*)d_out;

    int nb_n = (n + 255) / 256;
    int nb_e = (E + 255) / 256;
    int nc   = (n + 1023) / 1024;
    int gemm_grid = (n + 127) / 128;

    // graph preprocessing (CSR by dst + normalization coefs)
    k_init<<<nb_n, 256>>>(n);
    k_hist<<<nb_e, 256>>>(ei, w, E, n);
    k_dinv<<<nb_n, 256>>>(n);
    k_scanA<<<nc, 1024>>>(n);
    k_scanB<<<1, 128>>>(nc, n);
    k_scanC<<<nc, 1024>>>(n);
    k_fill<<<nb_e, 256>>>(ei, w, E, n);

    // layer 1: gemm(x) -> bufA, agg -> bufB, BN stats
    k_gemm<128><<<gemm_grid, 256>>>(x, 0, W1, 1, n, 0);
    k_agg<128><<<(n * 32 + 255) / 256, 256>>>(1, b1, nullptr, 2, n);
    k_zstats<<<1, 128>>>();
    k_stats<<<400, 256>>>(n);
    k_bnfin<<<1, 128>>>(gamma1, beta1, n);

    // layer 2: gemm(BN+ReLU(bufB)) -> bufA, agg -> bufB, BN stats
    k_gemm<128><<<gemm_grid, 256>>>(nullptr, 2, W2, 1, n, 1);
    k_agg<128><<<(n * 32 + 255) / 256, 256>>>(1, b2, nullptr, 2, n);
    k_zstats<<<1, 128>>>();
    k_stats<<<400, 256>>>(n);
    k_bnfin<<<1, 128>>>(gamma2, beta2, n);

    // layer 3: gemm(BN+ReLU(bufB)) -> bufA (64 cols), agg -> out
    k_gemm<64><<<gemm_grid, 256>>>(nullptr, 2, W3, 1, n, 1);
    k_agg<64><<<(n * 16 + 255) / 256, 256>>>(1, b3, out, 0, n);
}

// round 12
// speedup vs baseline: 1.2783x; 1.0674x over previous
#include <cuda_runtime.h>
#include <cuda_bf16.h>
#include <stdint.h>
#include <math.h>

#define NMAX 100000
#define EMAX 1600000

// ---------------- scratch (allocation-free: __device__ globals) ----------------
__device__ float    g_bufA[(size_t)NMAX * 128];
__device__ float    g_bufB[(size_t)NMAX * 128];
__device__ float    g_deg[NMAX];
__device__ float    g_dinv[NMAX];
__device__ int      g_cnt[NMAX];
__device__ int      g_fill[NMAX];
__device__ int      g_rowptr[NMAX + 1];
__device__ int      g_col[EMAX];
__device__ float    g_coef[EMAX];
__device__ int      g_csum[128];
__device__ float    g_sum[128];
__device__ float    g_sumsq[128];
__device__ float    g_scale[128];
__device__ float    g_shift[128];
// packed transposed split weights: [nn][k/2] bf16x2, row stride 64 (K=128)
// offsets: W1 at 0, W2 at 8192, W3 at 16384
__device__ uint32_t g_wh[3 * 128 * 64];
__device__ uint32_t g_wl[3 * 128 * 64];

__device__ __forceinline__ const float* sel_src(int s, const float* ext) {
    return (s == 0) ? ext : ((s == 1) ? g_bufA : g_bufB);
}
__device__ __forceinline__ float* sel_dst(int s, float* ext) {
    return (s == 0) ? ext : ((s == 1) ? g_bufA : g_bufB);
}

__device__ __forceinline__ void split_bf16(float f, __nv_bfloat16& h, __nv_bfloat16& l) {
    h = __float2bfloat16(f);
    l = __float2bfloat16(f - __bfloat162float(h));
}
__device__ __forceinline__ uint32_t pack_bf16(__nv_bfloat16 a, __nv_bfloat16 b) {
    return (uint32_t)__bfloat16_as_ushort(a) | ((uint32_t)__bfloat16_as_ushort(b) << 16);
}

// ---------------- weight pre-split/transpose/pack ----------------
// W is [K=128][NC] row-major fp32 -> outh/outl [nn][kk] uint32 (kk = k/2), stride 64
__global__ void k_packw(const float* __restrict__ W, int NC, int woff) {
    int idx = blockIdx.x * blockDim.x + threadIdx.x;
    if (idx >= NC * 64) return;
    int nn = idx >> 6;
    int kk = idx & 63;
    float a = W[(size_t)(2 * kk)     * NC + nn];
    float b = W[(size_t)(2 * kk + 1) * NC + nn];
    __nv_bfloat16 ha, la, hb, lb;
    split_bf16(a, ha, la);
    split_bf16(b, hb, lb);
    g_wh[woff + idx] = pack_bf16(ha, hb);
    g_wl[woff + idx] = pack_bf16(la, lb);
}

// ---------------- graph preprocessing ----------------
__global__ void k_init(int n) {
    int v = blockIdx.x * blockDim.x + threadIdx.x;
    if (v < n) { g_deg[v] = 1.0f; g_cnt[v] = 0; g_fill[v] = 0; }
}

__global__ void k_hist(const int* __restrict__ ei, const float* __restrict__ w, int E, int n) {
    int e = blockIdx.x * blockDim.x + threadIdx.x;
    if (e < E) {
        int dst = ei[E + e];
        if ((unsigned)dst < (unsigned)n) {
            atomicAdd(&g_deg[dst], w[e]);
            atomicAdd(&g_cnt[dst], 1);
        }
    }
}

__global__ void k_dinv(int n) {
    int v = blockIdx.x * blockDim.x + threadIdx.x;
    if (v < n) g_dinv[v] = rsqrtf(g_deg[v]);
}

__global__ void k_scanA(int n) {
    __shared__ int sh[1024];
    int t = threadIdx.x;
    int idx = blockIdx.x * 1024 + t;
    sh[t] = (idx < n) ? g_cnt[idx] : 0;
    __syncthreads();
    for (int off = 512; off > 0; off >>= 1) {
        if (t < off) sh[t] += sh[t + off];
        __syncthreads();
    }
    if (t == 0) g_csum[blockIdx.x] = sh[0];
}

__global__ void k_scanB(int nc, int n) {
    __shared__ int sh[128];
    int t = threadIdx.x;
    int v = (t < nc) ? g_csum[t] : 0;
    sh[t] = v; __syncthreads();
    for (int off = 1; off < 128; off <<= 1) {
        int x = (t >= off) ? sh[t - off] : 0;
        __syncthreads();
        sh[t] += x;
        __syncthreads();
    }
    if (t < nc) g_csum[t] = sh[t] - v;
    if (t == nc - 1) g_rowptr[n] = sh[t];
}

__global__ void k_scanC(int n) {
    __shared__ int sh[1024];
    int t = threadIdx.x;
    int idx = blockIdx.x * 1024 + t;
    int val = (idx < n) ? g_cnt[idx] : 0;
    sh[t] = val; __syncthreads();
    for (int off = 1; off < 1024; off <<= 1) {
        int x = (t >= off) ? sh[t - off] : 0;
        __syncthreads();
        sh[t] += x;
        __syncthreads();
    }
    if (idx < n) g_rowptr[idx] = g_csum[blockIdx.x] + sh[t] - val;
}

__global__ void k_fill(const int* __restrict__ ei, const float* __restrict__ w, int E, int n) {
    int e = blockIdx.x * blockDim.x + threadIdx.x;
    if (e < E) {
        int s = ei[e];
        int d = ei[E + e];
        if ((unsigned)s < (unsigned)n && (unsigned)d < (unsigned)n) {
            int pos = g_rowptr[d] + atomicAdd(&g_fill[d], 1);
            g_col[pos]  = s;
            g_coef[pos] = g_dinv[s] * w[e] * g_dinv[d];
        }
    }
}

// ---------------- tensor-core GEMM: [n,128] @ [128,NC] via bf16 split ----------------
// O = Xh*Wh + Xh*Wl + Xl*Wh.  W pre-split/packed in g_wh/g_wl.
// Smem packed bf16x2; row stride 20 words -> conflict-free frag loads.

__device__ __forceinline__ void mma16816(float* d, const uint32_t* a, const uint32_t* b) {
    asm volatile(
        "mma.sync.aligned.m16n8k16.row.col.f32.bf16.bf16.f32 "
        "{%0,%1,%2,%3}, {%4,%5,%6,%7}, {%8,%9}, {%0,%1,%2,%3};\n"
        : "+f"(d[0]), "+f"(d[1]), "+f"(d[2]), "+f"(d[3])
        : "r"(a[0]), "r"(a[1]), "r"(a[2]), "r"(a[3]), "r"(b[0]), "r"(b[1]));
}

template<int NC>
__global__ void k_gemm(const float* __restrict__ Xext, int xsel,
                       int wsel, int osel, int n, int useBN) {
    __shared__ uint32_t sAh[128][20];   // cols 0..15 used (k/2), pad to 20
    __shared__ uint32_t sAl[128][20];
    __shared__ uint32_t sBh[NC][20];
    __shared__ uint32_t sBl[NC][20];

    const float* X = sel_src(xsel, Xext);
    float*       O = sel_dst(osel, nullptr);
    const uint32_t* Wh = g_wh + wsel * 8192;
    const uint32_t* Wl = g_wl + wsel * 8192;

    const int t    = threadIdx.x;
    const int wid  = t >> 5;
    const int lane = t & 31;
    const int qr   = lane >> 2;        // 0..7
    const int qc   = (lane & 3) * 2;   // 0,2,4,6
    const int rowBase = blockIdx.x * 128;

    constexpr int M_TILES = (NC == 128) ? 2 : 1;
    const int mrow0 = (NC == 128) ? ((wid & 3) * 32) : (wid * 16);
    const int ncol0 = (NC == 128) ? ((wid >> 2) * 64) : 0;

    float d[M_TILES][8][4];
    #pragma unroll
    for (int mt = 0; mt < M_TILES; mt++)
        #pragma unroll
        for (int nt = 0; nt < 8; nt++)
            #pragma unroll
            for (int j = 0; j < 4; j++) d[mt][nt][j] = 0.f;

    const float4* X4 = (const float4*)X;

    for (int kc = 0; kc < 4; kc++) {
        // ---- A chunk: rows 0..127, k in [kc*32, kc*32+32): split+pack ----
        #pragma unroll
        for (int it = 0; it < 4; it++) {
            int r  = (t >> 3) + it * 32;
            int c4 = t & 7;
            int grow = rowBase + r;
            float4 v = make_float4(0.f, 0.f, 0.f, 0.f);
            if (grow < n) v = X4[(size_t)grow * 32 + kc * 8 + c4];
            if (useBN) {
                int k = kc * 32 + c4 * 4;
                v.x = fmaxf(fmaf(v.x, g_scale[k],     g_shift[k]),     0.f);
                v.y = fmaxf(fmaf(v.y, g_scale[k + 1], g_shift[k + 1]), 0.f);
                v.z = fmaxf(fmaf(v.z, g_scale[k + 2], g_shift[k + 2]), 0.f);
                v.w = fmaxf(fmaf(v.w, g_scale[k + 3], g_shift[k + 3]), 0.f);
            }
            __nv_bfloat16 h0,l0,h1,l1,h2,l2,h3,l3;
            split_bf16(v.x, h0, l0); split_bf16(v.y, h1, l1);
            split_bf16(v.z, h2, l2); split_bf16(v.w, h3, l3);
            sAh[r][c4 * 2]     = pack_bf16(h0, h1);
            sAh[r][c4 * 2 + 1] = pack_bf16(h2, h3);
            sAl[r][c4 * 2]     = pack_bf16(l0, l1);
            sAl[r][c4 * 2 + 1] = pack_bf16(l2, l3);
        }
        // ---- B chunk: straight copy of pre-packed W (cols kc*16 .. +16) ----
        #pragma unroll
        for (int i = t; i < NC * 16; i += 256) {
            int nn = i >> 4;
            int j  = i & 15;
            sBh[nn][j] = Wh[nn * 64 + kc * 16 + j];
            sBl[nn][j] = Wl[nn * 64 + kc * 16 + j];
        }
        __syncthreads();

        // ---- 2 k-steps of 16 ----
        #pragma unroll
        for (int ks = 0; ks < 2; ks++) {
            int kb2 = ks * 8 + (qc >> 1);       // (kb+qc)/2
            uint32_t ah[M_TILES][4], al[M_TILES][4];
            #pragma unroll
            for (int mt = 0; mt < M_TILES; mt++) {
                int r0 = mrow0 + mt * 16 + qr;
                ah[mt][0] = sAh[r0    ][kb2];
                ah[mt][1] = sAh[r0 + 8][kb2];
                ah[mt][2] = sAh[r0    ][kb2 + 4];
                ah[mt][3] = sAh[r0 + 8][kb2 + 4];
                al[mt][0] = sAl[r0    ][kb2];
                al[mt][1] = sAl[r0 + 8][kb2];
                al[mt][2] = sAl[r0    ][kb2 + 4];
                al[mt][3] = sAl[r0 + 8][kb2 + 4];
            }
            uint32_t bh[8][2], bl[8][2];
            #pragma unroll
            for (int nt = 0; nt < 8; nt++) {
                int n0 = ncol0 + nt * 8 + qr;
                bh[nt][0] = sBh[n0][kb2];
                bh[nt][1] = sBh[n0][kb2 + 4];
                bl[nt][0] = sBl[n0][kb2];
                bl[nt][1] = sBl[n0][kb2 + 4];
            }
            #pragma unroll
            for (int mt = 0; mt < M_TILES; mt++)
                #pragma unroll
                for (int nt = 0; nt < 8; nt++) {
                    mma16816(d[mt][nt], ah[mt], bh[nt]);
                    mma16816(d[mt][nt], ah[mt], bl[nt]);
                    mma16816(d[mt][nt], al[mt], bh[nt]);
                }
        }
        __syncthreads();
    }

    // ---- epilogue ----
    #pragma unroll
    for (int mt = 0; mt < M_TILES; mt++) {
        #pragma unroll
        for (int nt = 0; nt < 8; nt++) {
            int r = rowBase + mrow0 + mt * 16 + qr;
            int c = ncol0 + nt * 8 + qc;
            if (r < n)
                *(float2*)&O[(size_t)r * NC + c] = make_float2(d[mt][nt][0], d[mt][nt][1]);
            if (r + 8 < n)
                *(float2*)&O[(size_t)(r + 8) * NC + c] = make_float2(d[mt][nt][2], d[mt][nt][3]);
        }
    }
}

// ---------------- aggregation: out[v] = sum_in coef*h[src] + dinv[v]^2*h[v] + bias ----------------
// TPN = D/4 threads per node; unroll-4 with dual accumulators for MLP=4.
template<int D>
__global__ void k_agg(int hsel, const float* __restrict__ bias,
                      float* __restrict__ Oext, int osel, int n) {
    const int TPN = D / 4;
    const int NPB = 256 / TPN;
    int t    = threadIdx.x;
    int v    = blockIdx.x * NPB + t / TPN;
    int lane = t % TPN;
    if (v >= n) return;

    const float4* H4 = (const float4*)sel_src(hsel, nullptr);
    float4*       O4 = (float4*)sel_dst(osel, Oext);

    float dv = g_dinv[v];
    float sc = dv * dv;
    float4 h = H4[(size_t)v * TPN + lane];
    float4 acc  = make_float4(h.x * sc, h.y * sc, h.z * sc, h.w * sc);
    float4 acc2 = make_float4(0.f, 0.f, 0.f, 0.f);

    int p   = g_rowptr[v];
    int end = g_rowptr[v + 1];
    for (; p + 4 <= end; p += 4) {
        int c0 = g_col[p];     float w0 = g_coef[p];
        int c1 = g_col[p + 1]; float w1 = g_coef[p + 1];
        int c2 = g_col[p + 2]; float w2 = g_coef[p + 2];
        int c3 = g_col[p + 3]; float w3 = g_coef[p + 3];
        float4 m0 = H4[(size_t)c0 * TPN + lane];
        float4 m1 = H4[(size_t)c1 * TPN + lane];
        float4 m2 = H4[(size_t)c2 * TPN + lane];
        float4 m3 = H4[(size_t)c3 * TPN + lane];
        acc.x  = fmaf(w0, m0.x, acc.x);  acc.y  = fmaf(w0, m0.y, acc.y);
        acc.z  = fmaf(w0, m0.z, acc.z);  acc.w  = fmaf(w0, m0.w, acc.w);
        acc2.x = fmaf(w1, m1.x, acc2.x); acc2.y = fmaf(w1, m1.y, acc2.y);
        acc2.z = fmaf(w1, m1.z, acc2.z); acc2.w = fmaf(w1, m1.w, acc2.w);
        acc.x  = fmaf(w2, m2.x, acc.x);  acc.y  = fmaf(w2, m2.y, acc.y);
        acc.z  = fmaf(w2, m2.z, acc.z);  acc.w  = fmaf(w2, m2.w, acc.w);
        acc2.x = fmaf(w3, m3.x, acc2.x); acc2.y = fmaf(w3, m3.y, acc2.y);
        acc2.z = fmaf(w3, m3.z, acc2.z); acc2.w = fmaf(w3, m3.w, acc2.w);
    }
    for (; p < end; p++) {
        int c = g_col[p]; float w = g_coef[p];
        float4 m = H4[(size_t)c * TPN + lane];
        acc.x = fmaf(w, m.x, acc.x); acc.y = fmaf(w, m.y, acc.y);
        acc.z = fmaf(w, m.z, acc.z); acc.w = fmaf(w, m.w, acc.w);
    }
    acc.x += acc2.x; acc.y += acc2.y; acc.z += acc2.z; acc.w += acc2.w;

    float4 b4 = ((const float4*)bias)[lane];
    acc.x += b4.x; acc.y += b4.y; acc.z += b4.z; acc.w += b4.w;
    O4[(size_t)v * TPN + lane] = acc;
}

// ---------------- BatchNorm stats / finalize (stats always on g_bufB) ----------------
__global__ void k_zstats() {
    int c = threadIdx.x;
    g_sum[c] = 0.f; g_sumsq[c] = 0.f;
}

__global__ void k_stats(int n) {
    int t = threadIdx.x;
    int col = t & 127;
    int phase = t >> 7;
    float s = 0.f, sq = 0.f;
    for (int r = blockIdx.x * 2 + phase; r < n; r += gridDim.x * 2) {
        float v = g_bufB[(size_t)r * 128 + col];
        s += v; sq += v * v;
    }
    __shared__ float ssum[256], ssq[256];
    ssum[t] = s; ssq[t] = sq;
    __syncthreads();
    if (t < 128) {
        atomicAdd(&g_sum[t],   ssum[t] + ssum[t + 128]);
        atomicAdd(&g_sumsq[t], ssq[t]  + ssq[t + 128]);
    }
}

__global__ void k_bnfin(const float* __restrict__ gamma, const float* __restrict__ beta, int n) {
    int c = threadIdx.x;
    double mean = (double)g_sum[c] / (double)n;
    double var  = (double)g_sumsq[c] / (double)n - mean * mean;
    float s = (float)((double)gamma[c] / sqrt(var + 1e-5));
    g_scale[c] = s;
    g_shift[c] = (float)((double)beta[c] - mean * (double)s);
}

// ---------------- launcher ----------------
extern "C" void kernel_launch(void* const* d_in, const int* in_sizes, int n_in,
                              void* d_out, int out_size) {
    const float* x  = (const float*)d_in[0];
    const int*   ei = (const int*)d_in[1];     // int32 [2, E]
    const float* w  = (const float*)d_in[2];
    const float* W1 = (const float*)d_in[3];
    const float* b1 = (const float*)d_in[4];
    const float* W2 = (const float*)d_in[5];
    const float* b2 = (const float*)d_in[6];
    const float* W3 = (const float*)d_in[7];
    const float* b3 = (const float*)d_in[8];
    const float* gamma1 = (const float*)d_in[9];
    const float* beta1  = (const float*)d_in[10];
    const float* gamma2 = (const float*)d_in[11];
    const float* beta2  = (const float*)d_in[12];

    int n = in_sizes[0] / 128;
    int E = in_sizes[1] / 2;
    float* out = (float*)d_out;

    int nb_n = (n + 255) / 256;
    int nb_e = (E + 255) / 256;
    int nc   = (n + 1023) / 1024;
    int gemm_grid = (n + 127) / 128;

    // weight pre-split/pack (once per call; tiny)
    k_packw<<<(128 * 64 + 255) / 256, 256>>>(W1, 128, 0);
    k_packw<<<(128 * 64 + 255) / 256, 256>>>(W2, 128, 8192);
    k_packw<<<(64 * 64 + 255) / 256, 256>>>(W3, 64, 16384);

    // graph preprocessing (CSR by dst + normalization coefs)
    k_init<<<nb_n, 256>>>(n);
    k_hist<<<nb_e, 256>>>(ei, w, E, n);
    k_dinv<<<nb_n, 256>>>(n);
    k_scanA<<<nc, 1024>>>(n);
    k_scanB<<<1, 128>>>(nc, n);
    k_scanC<<<nc, 1024>>>(n);
    k_fill<<<nb_e, 256>>>(ei, w, E, n);

    // layer 1: gemm(x) -> bufA, agg -> bufB, BN stats
    k_gemm<128><<<gemm_grid, 256>>>(x, 0, 0, 1, n, 0);
    k_agg<128><<<(n + 7) / 8, 256>>>(1, b1, nullptr, 2, n);
    k_zstats<<<1, 128>>>();
    k_stats<<<400, 256>>>(n);
    k_bnfin<<<1, 128>>>(gamma1, beta1, n);

    // layer 2: gemm(BN+ReLU(bufB)) -> bufA, agg -> bufB, BN stats
    k_gemm<128><<<gemm_grid, 256>>>(nullptr, 2, 1, 1, n, 1);
    k_agg<128><<<(n + 7) / 8, 256>>>(1, b2, nullptr, 2, n);
    k_zstats<<<1, 128>>>();
    k_stats<<<400, 256>>>(n);
    k_bnfin<<<1, 128>>>(gamma2, beta2, n);

    // layer 3: gemm(BN+ReLU(bufB)) -> bufA (64 cols), agg -> out
    k_gemm<64><<<gemm_grid, 256>>>(nullptr, 2, 2, 1, n, 1);
    k_agg<64><<<(n + 15) / 16, 256>>>(1, b3, out, 0, n);
}